// round 3
// baseline (speedup 1.0000x reference)
#include <cuda_runtime.h>
#include <math.h>

#define B_    4
#define T_    2048
#define C_    1024
#define H_    16
#define D_    64
#define WIN_  256
#define QB    16

// Scratch (device globals; no runtime allocation allowed)
__device__ float g_q[B_*H_*T_*D_];
__device__ float g_k[B_*H_*T_*D_];
__device__ float g_v[B_*H_*T_*D_];
__device__ float g_att[B_*T_*C_];

// ---------------------------------------------------------------------------
// Tiled fp32 GEMM, NT form: C[m,n] = sum_k A[m,k] * Bw[n,k] + bias[n]
// BM=BN=128, BK=16, 256 threads, 8x8 per thread.
// MODE 0: plain row-major write to Cout [M,N], A passed as arg
// MODE 1: scatter qkv columns into g_q/g_k/g_v laid out [B,H,T,D]
// MODE 2: like MODE 0 but A = g_att (device global; must NOT be passed
//         from host — host-side symbol is the shadow copy, and GB300's
//         ATS silently reads it as zeros instead of faulting)
// ---------------------------------------------------------------------------
#define BM 128
#define BN 128
#define BK 16

template<int MODE>
__global__ __launch_bounds__(256, 2) void sgemm_nt(
    const float* __restrict__ Aarg,
    const float* __restrict__ Bw,
    const float* __restrict__ bias,
    float* __restrict__ Cout,
    int M, int N, int K)
{
    __shared__ float As[BK][BM + 4];
    __shared__ float Bs[BK][BN + 4];

    const float* __restrict__ A = (MODE == 2) ? (const float*)g_att : Aarg;

    const int tid = threadIdx.x;
    const int tx  = tid & 15;   // 0..15 -> n
    const int ty  = tid >> 4;   // 0..15 -> m
    const int m0  = blockIdx.y * BM;
    const int n0  = blockIdx.x * BN;

    float acc[8][8];
    #pragma unroll
    for (int i = 0; i < 8; i++)
        #pragma unroll
        for (int j = 0; j < 8; j++) acc[i][j] = 0.f;

    for (int k0 = 0; k0 < K; k0 += BK) {
        // 512 float4 per tile for A and for B; each thread does 2 of each.
        #pragma unroll
        for (int f = tid; f < 512; f += 256) {
            int row = f >> 2;
            int c4  = (f & 3) << 2;
            float4 va = *(const float4*)&A [(long)(m0 + row) * K + k0 + c4];
            As[c4+0][row] = va.x; As[c4+1][row] = va.y;
            As[c4+2][row] = va.z; As[c4+3][row] = va.w;
            float4 vb = *(const float4*)&Bw[(long)(n0 + row) * K + k0 + c4];
            Bs[c4+0][row] = vb.x; Bs[c4+1][row] = vb.y;
            Bs[c4+2][row] = vb.z; Bs[c4+3][row] = vb.w;
        }
        __syncthreads();

        #pragma unroll
        for (int kk = 0; kk < BK; kk++) {
            float a[8], bb[8];
            *(float4*)&a[0]  = *(const float4*)&As[kk][ty * 8];
            *(float4*)&a[4]  = *(const float4*)&As[kk][ty * 8 + 4];
            *(float4*)&bb[0] = *(const float4*)&Bs[kk][tx * 8];
            *(float4*)&bb[4] = *(const float4*)&Bs[kk][tx * 8 + 4];
            #pragma unroll
            for (int i = 0; i < 8; i++)
                #pragma unroll
                for (int j = 0; j < 8; j++)
                    acc[i][j] += a[i] * bb[j];
        }
        __syncthreads();
    }

    #pragma unroll
    for (int i = 0; i < 8; i++) {
        const int m = m0 + ty * 8 + i;
        #pragma unroll
        for (int j = 0; j < 8; j++) {
            const int n = n0 + tx * 8 + j;
            float v = acc[i][j] + bias[n];
            if (MODE == 1) {
                // n in [0,3072): s = n/1024, h = (n/64)%16, d = n%64
                int s = n >> 10;
                int h = (n >> 6) & 15;
                int d = n & 63;
                int b = m >> 11;   // T_ = 2048
                int t = m & 2047;
                float* dst = (s == 0) ? g_q : (s == 1 ? g_k : g_v);
                dst[(((long)(b * H_ + h)) * T_ + t) * D_ + d] = v;
            } else {
                Cout[(long)m * N + n] = v;
            }
        }
    }
}

// ---------------------------------------------------------------------------
// Windowed causal attention. Block = 512 threads (16 warps), handles QB=16
// consecutive queries of one (b,h). Warp w owns query q0+w. Keys staged in
// smem in chunks of 32; lane l scores key chunk_start+l; online softmax;
// PV via shfl broadcast, lane l accumulates output dims 2l, 2l+1.
// ---------------------------------------------------------------------------
__global__ __launch_bounds__(512) void attn_win_kernel()
{
    __shared__ float q_s[QB][64];
    __shared__ float k_s[32][68];   // +4 pad: conflict-free LDS.128 per-lane rows
    __shared__ float v_s[32][64];

    const int tid  = threadIdx.x;
    const int w    = tid >> 5;
    const int lane = tid & 31;
    const int q0   = blockIdx.x * QB;
    const int h    = blockIdx.y;
    const int b    = blockIdx.z;

    const long bh   = (long)(b * H_ + h);
    const float* Qp = g_q + bh * T_ * D_;
    const float* Kp = g_k + bh * T_ * D_;
    const float* Vp = g_v + bh * T_ * D_;

    // Load Q tile: 16 x 64 floats = 256 float4
    if (tid < 256) {
        int r  = tid >> 4;
        int c4 = (tid & 15) << 2;
        *(float4*)&q_s[r][c4] = *(const float4*)&Qp[(long)(q0 + r) * D_ + c4];
    }

    const int qi = q0 + w;
    int lo_blk = q0 - (WIN_ - 1);
    if (lo_blk < 0) lo_blk = 0;
    lo_blk &= ~31;
    const int nchunks = ((q0 + QB - 1) - lo_blk) / 32 + 1;

    float m_run = -1e30f, l_run = 0.f;
    float accx = 0.f, accy = 0.f;

    for (int c = 0; c < nchunks; c++) {
        const int ks = lo_blk + c * 32;
        __syncthreads();
        {   // stage K and V chunk: 32 keys x 64 dims each = 512 float4 apiece
            int r  = tid >> 4;
            int c4 = (tid & 15) << 2;
            int j  = ks + r;
            float4 kv = make_float4(0.f, 0.f, 0.f, 0.f);
            float4 vv = make_float4(0.f, 0.f, 0.f, 0.f);
            if (j < T_) {
                kv = *(const float4*)&Kp[(long)j * D_ + c4];
                vv = *(const float4*)&Vp[(long)j * D_ + c4];
            }
            *(float4*)&k_s[r][c4] = kv;
            *(float4*)&v_s[r][c4] = vv;
        }
        __syncthreads();

        // Per-warp skip if chunk entirely outside this query's window
        if (ks > qi || ks + 31 < qi - (WIN_ - 1)) continue;

        const int j = ks + lane;
        const bool valid = (j <= qi) && (qi - j < WIN_);

        float dot = 0.f;
        #pragma unroll
        for (int d4 = 0; d4 < 16; d4++) {
            float4 qv = *(const float4*)&q_s[w][d4 * 4];
            float4 kk = *(const float4*)&k_s[lane][d4 * 4];
            dot += qv.x * kk.x + qv.y * kk.y + qv.z * kk.z + qv.w * kk.w;
        }
        float s = valid ? dot * 0.125f : -1e30f;

        // warp max
        float cm = s;
        #pragma unroll
        for (int off = 16; off > 0; off >>= 1)
            cm = fmaxf(cm, __shfl_xor_sync(0xffffffffu, cm, off));

        const float m_new = fmaxf(m_run, cm);
        const float corr  = __expf(m_run - m_new);
        float p = valid ? __expf(s - m_new) : 0.f;

        float ps = p;
        #pragma unroll
        for (int off = 16; off > 0; off >>= 1)
            ps += __shfl_xor_sync(0xffffffffu, ps, off);

        l_run = l_run * corr + ps;
        accx *= corr;
        accy *= corr;
        m_run = m_new;

        #pragma unroll
        for (int jj = 0; jj < 32; jj++) {
            float pj = __shfl_sync(0xffffffffu, p, jj);
            float2 vv = *(const float2*)&v_s[jj][lane * 2];
            accx += pj * vv.x;
            accy += pj * vv.y;
        }
    }

    // out laid out [B,T,H,D] == [B,T,C] for the proj GEMM
    const float inv = 1.f / l_run;
    float2 o;
    o.x = accx * inv;
    o.y = accy * inv;
    *(float2*)&g_att[((long)(b * T_ + qi)) * C_ + h * D_ + lane * 2] = o;
}

// ---------------------------------------------------------------------------
// Launch. Inputs identified by element count (all distinct):
//   x: 8388608, attn_mask: 4194304, qkv_w: 3145728, qkv_b: 3072,
//   proj_w: 1048576, proj_b: 1024
// NOTE: device globals (g_att etc.) are never passed as kernel args from
// host — host code only sees the shadow symbol (silently readable as zeros
// on GB300 via ATS). They are bound inside device code via MODE.
// ---------------------------------------------------------------------------
extern "C" void kernel_launch(void* const* d_in, const int* in_sizes, int n_in,
                              void* d_out, int out_size)
{
    const float* x      = 0;
    const float* qkv_w  = 0;
    const float* qkv_b  = 0;
    const float* proj_w = 0;
    const float* proj_b = 0;

    for (int i = 0; i < n_in; i++) {
        switch (in_sizes[i]) {
            case B_ * T_ * C_:  x      = (const float*)d_in[i]; break; // 8388608
            case T_ * T_:       /* attn_mask (bool) — unused */  break; // 4194304
            case 3 * C_ * C_:   qkv_w  = (const float*)d_in[i]; break; // 3145728
            case 3 * C_:        qkv_b  = (const float*)d_in[i]; break; // 3072
            case C_ * C_:       proj_w = (const float*)d_in[i]; break; // 1048576
            case C_:            proj_b = (const float*)d_in[i]; break; // 1024
        }
    }

    float* out = (float*)d_out;

    // QKV: [8192,1024] x [3072,1024]^T -> scatter to g_q/g_k/g_v
    {
        dim3 grid(3 * C_ / BN, (B_ * T_) / BM);
        sgemm_nt<1><<<grid, 256>>>(x, qkv_w, qkv_b, nullptr,
                                   B_ * T_, 3 * C_, C_);
    }
    // Attention
    {
        dim3 grid(T_ / QB, H_, B_);
        attn_win_kernel<<<grid, 512>>>();
    }
    // Proj: g_att [8192,1024] x [1024,1024]^T -> out (A bound in-device)
    {
        dim3 grid(C_ / BN, (B_ * T_) / BM);
        sgemm_nt<2><<<grid, 256>>>(nullptr, proj_w, proj_b, out,
                                   B_ * T_, C_, C_);
    }
}

// round 4
// speedup vs baseline: 1.4257x; 1.4257x over previous
#include <cuda_runtime.h>
#include <math.h>
#include <stdint.h>

#define B_    4
#define T_    2048
#define C_    1024
#define H_    16
#define D_    64
#define WIN_  256
#define QB    16

// Scratch (device globals; no runtime allocation allowed)
__device__ float g_q[B_*H_*T_*D_];
__device__ float g_k[B_*H_*T_*D_];
__device__ float g_v[B_*H_*T_*D_];
__device__ float g_att[B_*T_*C_];

// ---------------------------------------------------------------------------
// tf32 tensor-core GEMM, NT form: C[m,n] = sum_k A[m,k] * Bw[n,k] + bias[n]
// Block tile 128x128x32, 256 threads (8 warps), warp tile 64x32
// (4x4 grid of m16n8k8 tf32 mma per 8-wide k-chunk).
// MODE 0: plain row-major write to Cout [M,N]
// MODE 1: scatter qkv columns into g_q/g_k/g_v laid out [B,H,T,D]
// MODE 2: like MODE 0 but A = g_att (bound in device code; host must never
//         pass a __device__ symbol — ATS silently reads the host shadow)
// ---------------------------------------------------------------------------

__device__ __forceinline__ uint32_t f2tf32(float x) {
    uint32_t r;
    asm("cvt.rna.tf32.f32 %0, %1;" : "=r"(r) : "f"(x));
    return r;
}

__device__ __forceinline__ void mma_tf32_16x8x8(
    float* d, const uint32_t* a, const uint32_t* b)
{
    asm volatile(
        "mma.sync.aligned.m16n8k8.row.col.f32.tf32.tf32.f32 "
        "{%0,%1,%2,%3}, {%4,%5,%6,%7}, {%8,%9}, {%0,%1,%2,%3};"
        : "+f"(d[0]), "+f"(d[1]), "+f"(d[2]), "+f"(d[3])
        : "r"(a[0]), "r"(a[1]), "r"(a[2]), "r"(a[3]),
          "r"(b[0]), "r"(b[1]));
}

// Smem row padded to 136: qid rows (stride 136) land at bank offsets
// {0,8,16,24} mod 32 -> conflict-free fragment loads.
#define SPAD 136

template<int MODE>
__global__ __launch_bounds__(256, 2) void gemm_tf32(
    const float* __restrict__ Aarg,
    const float* __restrict__ Bw,
    const float* __restrict__ bias,
    float* __restrict__ Cout,
    int M, int N, int K)
{
    __shared__ uint32_t As[32][SPAD];   // [k][m], tf32 bits
    __shared__ uint32_t Bs[32][SPAD];   // [k][n], tf32 bits

    const float* __restrict__ A = (MODE == 2) ? (const float*)g_att : Aarg;

    const int tid  = threadIdx.x;
    const int w    = tid >> 5;
    const int lane = tid & 31;
    const int gid  = lane >> 2;   // 0..7
    const int qid  = lane & 3;    // 0..3
    const int wm   = w & 1;       // 2 warp-rows of 64
    const int wn   = w >> 1;      // 4 warp-cols of 32
    const int m0   = blockIdx.y * 128;
    const int n0   = blockIdx.x * 128;

    float acc[4][4][4];
    #pragma unroll
    for (int i = 0; i < 4; i++)
        #pragma unroll
        for (int j = 0; j < 4; j++)
            #pragma unroll
            for (int r = 0; r < 4; r++) acc[i][j][r] = 0.f;

    for (int k0 = 0; k0 < K; k0 += 32) {
        // Stage tiles: 128 rows x 32 k-floats each = 1024 float4 apiece.
        #pragma unroll
        for (int f = tid; f < 1024; f += 256) {
            int row = f >> 3;          // 0..127
            int c4  = (f & 7) << 2;    // 0,4,...,28
            float4 va = *(const float4*)&A [(long)(m0 + row) * K + k0 + c4];
            As[c4+0][row] = f2tf32(va.x); As[c4+1][row] = f2tf32(va.y);
            As[c4+2][row] = f2tf32(va.z); As[c4+3][row] = f2tf32(va.w);
            float4 vb = *(const float4*)&Bw[(long)(n0 + row) * K + k0 + c4];
            Bs[c4+0][row] = f2tf32(vb.x); Bs[c4+1][row] = f2tf32(vb.y);
            Bs[c4+2][row] = f2tf32(vb.z); Bs[c4+3][row] = f2tf32(vb.w);
        }
        __syncthreads();

        #pragma unroll
        for (int kk = 0; kk < 4; kk++) {
            const int kb = kk * 8;
            uint32_t af[4][4], bf[4][2];
            #pragma unroll
            for (int im = 0; im < 4; im++) {
                const int mr = wm * 64 + im * 16 + gid;
                af[im][0] = As[kb + qid    ][mr];
                af[im][1] = As[kb + qid    ][mr + 8];
                af[im][2] = As[kb + qid + 4][mr];
                af[im][3] = As[kb + qid + 4][mr + 8];
            }
            #pragma unroll
            for (int in = 0; in < 4; in++) {
                const int nc = wn * 32 + in * 8 + gid;
                bf[in][0] = Bs[kb + qid    ][nc];
                bf[in][1] = Bs[kb + qid + 4][nc];
            }
            #pragma unroll
            for (int im = 0; im < 4; im++)
                #pragma unroll
                for (int in = 0; in < 4; in++)
                    mma_tf32_16x8x8(acc[im][in], af[im], bf[in]);
        }
        __syncthreads();
    }

    // Epilogue. Accumulator layout per mma tile:
    //   c0:(gid, 2q)  c1:(gid, 2q+1)  c2:(gid+8, 2q)  c3:(gid+8, 2q+1)
    #pragma unroll
    for (int im = 0; im < 4; im++) {
        #pragma unroll
        for (int in = 0; in < 4; in++) {
            const int mbase = m0 + wm * 64 + im * 16 + gid;
            const int nbase = n0 + wn * 32 + in * 8 + qid * 2;
            #pragma unroll
            for (int r = 0; r < 4; r++) {
                const int m = mbase + (r >> 1) * 8;
                const int n = nbase + (r & 1);
                float v = acc[im][in][r] + bias[n];
                if (MODE == 1) {
                    // n in [0,3072): s=n/1024, h=(n/64)%16, d=n%64
                    int s = n >> 10;
                    int h = (n >> 6) & 15;
                    int d = n & 63;
                    int b = m >> 11;     // T_ = 2048
                    int t = m & 2047;
                    float* dst = (s == 0) ? g_q : (s == 1 ? g_k : g_v);
                    dst[(((long)(b * H_ + h)) * T_ + t) * D_ + d] = v;
                } else {
                    Cout[(long)m * N + n] = v;
                }
            }
        }
    }
}

// ---------------------------------------------------------------------------
// Windowed causal attention (unchanged). Block = 512 threads, QB=16 queries
// of one (b,h); warp w owns query q0+w; keys staged in smem chunks of 32;
// online softmax; PV via shfl broadcast.
// ---------------------------------------------------------------------------
__global__ __launch_bounds__(512) void attn_win_kernel()
{
    __shared__ float q_s[QB][64];
    __shared__ float k_s[32][68];
    __shared__ float v_s[32][64];

    const int tid  = threadIdx.x;
    const int w    = tid >> 5;
    const int lane = tid & 31;
    const int q0   = blockIdx.x * QB;
    const int h    = blockIdx.y;
    const int b    = blockIdx.z;

    const long bh   = (long)(b * H_ + h);
    const float* Qp = g_q + bh * T_ * D_;
    const float* Kp = g_k + bh * T_ * D_;
    const float* Vp = g_v + bh * T_ * D_;

    if (tid < 256) {
        int r  = tid >> 4;
        int c4 = (tid & 15) << 2;
        *(float4*)&q_s[r][c4] = *(const float4*)&Qp[(long)(q0 + r) * D_ + c4];
    }

    const int qi = q0 + w;
    int lo_blk = q0 - (WIN_ - 1);
    if (lo_blk < 0) lo_blk = 0;
    lo_blk &= ~31;
    const int nchunks = ((q0 + QB - 1) - lo_blk) / 32 + 1;

    float m_run = -1e30f, l_run = 0.f;
    float accx = 0.f, accy = 0.f;

    for (int c = 0; c < nchunks; c++) {
        const int ks = lo_blk + c * 32;
        __syncthreads();
        {
            int r  = tid >> 4;
            int c4 = (tid & 15) << 2;
            int j  = ks + r;
            float4 kv = make_float4(0.f, 0.f, 0.f, 0.f);
            float4 vv = make_float4(0.f, 0.f, 0.f, 0.f);
            if (j < T_) {
                kv = *(const float4*)&Kp[(long)j * D_ + c4];
                vv = *(const float4*)&Vp[(long)j * D_ + c4];
            }
            *(float4*)&k_s[r][c4] = kv;
            *(float4*)&v_s[r][c4] = vv;
        }
        __syncthreads();

        if (ks > qi || ks + 31 < qi - (WIN_ - 1)) continue;

        const int j = ks + lane;
        const bool valid = (j <= qi) && (qi - j < WIN_);

        float dot = 0.f;
        #pragma unroll
        for (int d4 = 0; d4 < 16; d4++) {
            float4 qv = *(const float4*)&q_s[w][d4 * 4];
            float4 kk = *(const float4*)&k_s[lane][d4 * 4];
            dot += qv.x * kk.x + qv.y * kk.y + qv.z * kk.z + qv.w * kk.w;
        }
        float s = valid ? dot * 0.125f : -1e30f;

        float cm = s;
        #pragma unroll
        for (int off = 16; off > 0; off >>= 1)
            cm = fmaxf(cm, __shfl_xor_sync(0xffffffffu, cm, off));

        const float m_new = fmaxf(m_run, cm);
        const float corr  = __expf(m_run - m_new);
        float p = valid ? __expf(s - m_new) : 0.f;

        float ps = p;
        #pragma unroll
        for (int off = 16; off > 0; off >>= 1)
            ps += __shfl_xor_sync(0xffffffffu, ps, off);

        l_run = l_run * corr + ps;
        accx *= corr;
        accy *= corr;
        m_run = m_new;

        #pragma unroll
        for (int jj = 0; jj < 32; jj++) {
            float pj = __shfl_sync(0xffffffffu, p, jj);
            float2 vv = *(const float2*)&v_s[jj][lane * 2];
            accx += pj * vv.x;
            accy += pj * vv.y;
        }
    }

    const float inv = 1.f / l_run;
    float2 o;
    o.x = accx * inv;
    o.y = accy * inv;
    *(float2*)&g_att[((long)(b * T_ + qi)) * C_ + h * D_ + lane * 2] = o;
}

// ---------------------------------------------------------------------------
// Launch. Inputs identified by element count (all distinct).
// ---------------------------------------------------------------------------
extern "C" void kernel_launch(void* const* d_in, const int* in_sizes, int n_in,
                              void* d_out, int out_size)
{
    const float* x      = 0;
    const float* qkv_w  = 0;
    const float* qkv_b  = 0;
    const float* proj_w = 0;
    const float* proj_b = 0;

    for (int i = 0; i < n_in; i++) {
        switch (in_sizes[i]) {
            case B_ * T_ * C_:  x      = (const float*)d_in[i]; break; // 8388608
            case T_ * T_:       /* attn_mask — unused */         break; // 4194304
            case 3 * C_ * C_:   qkv_w  = (const float*)d_in[i]; break; // 3145728
            case 3 * C_:        qkv_b  = (const float*)d_in[i]; break; // 3072
            case C_ * C_:       proj_w = (const float*)d_in[i]; break; // 1048576
            case C_:            proj_b = (const float*)d_in[i]; break; // 1024
        }
    }

    float* out = (float*)d_out;

    // QKV: [8192,1024] x [3072,1024]^T -> scatter to g_q/g_k/g_v
    {
        dim3 grid(3 * C_ / 128, (B_ * T_) / 128);
        gemm_tf32<1><<<grid, 256>>>(x, qkv_w, qkv_b, nullptr,
                                    B_ * T_, 3 * C_, C_);
    }
    // Attention
    {
        dim3 grid(T_ / QB, H_, B_);
        attn_win_kernel<<<grid, 512>>>();
    }
    // Proj: g_att [8192,1024] x [1024,1024]^T -> out
    {
        dim3 grid(C_ / 128, (B_ * T_) / 128);
        gemm_tf32<2><<<grid, 256>>>(nullptr, proj_w, proj_b, out,
                                    B_ * T_, C_, C_);
    }
}

// round 6
// speedup vs baseline: 1.6751x; 1.1749x over previous
#include <cuda_runtime.h>
#include <math.h>
#include <stdint.h>

#define B_    4
#define T_    2048
#define C_    1024
#define H_    16
#define D_    64
#define WIN_  256

// Scratch (device globals; no runtime allocation allowed)
__device__ float g_q[B_*H_*T_*D_];
__device__ float g_k[B_*H_*T_*D_];
__device__ float g_v[B_*H_*T_*D_];
__device__ float g_att[B_*T_*C_];

// ---------------------------------------------------------------------------
// tf32 tensor-core GEMM, NT form: C[m,n] = sum_k A[m,k] * Bw[n,k] + bias[n]
// Block tile 128x128x32, 256 threads (8 warps), warp tile 64x32.
// Staging is bank-conflict-free: lane-varying row (banks 4i+r all distinct),
// fragment loads conflict-free via SPAD=136 (banks 8*qid+gid all distinct).
// Register prefetch of next k-chunk overlaps LDG latency with the mma loop.
// MODE 0: plain write. MODE 1: qkv scatter. MODE 2: A = g_att (device-bound).
// ---------------------------------------------------------------------------

__device__ __forceinline__ uint32_t f2tf32(float x) {
    uint32_t r;
    asm("cvt.rna.tf32.f32 %0, %1;" : "=r"(r) : "f"(x));
    return r;
}

__device__ __forceinline__ void mma_tf32_16x8x8(
    float* d, const uint32_t* a, const uint32_t* b)
{
    asm volatile(
        "mma.sync.aligned.m16n8k8.row.col.f32.tf32.tf32.f32 "
        "{%0,%1,%2,%3}, {%4,%5,%6,%7}, {%8,%9}, {%0,%1,%2,%3};"
        : "+f"(d[0]), "+f"(d[1]), "+f"(d[2]), "+f"(d[3])
        : "r"(a[0]), "r"(a[1]), "r"(a[2]), "r"(a[3]),
          "r"(b[0]), "r"(b[1]));
}

#define SPAD 136

template<int MODE>
__global__ __launch_bounds__(256, 2) void gemm_tf32(
    const float* __restrict__ Aarg,
    const float* __restrict__ Bw,
    const float* __restrict__ bias,
    float* __restrict__ Cout,
    int M, int N, int K)
{
    __shared__ uint32_t As[32][SPAD];   // [k][m], tf32 bits
    __shared__ uint32_t Bs[32][SPAD];   // [k][n], tf32 bits

    const float* __restrict__ A = (MODE == 2) ? (const float*)g_att : Aarg;

    const int tid  = threadIdx.x;
    const int w    = tid >> 5;
    const int lane = tid & 31;
    const int gid  = lane >> 2;   // 0..7
    const int qid  = lane & 3;    // 0..3
    const int wm   = w & 1;       // 2 warp-rows of 64
    const int wn   = w >> 1;      // 4 warp-cols of 32
    const int m0   = blockIdx.y * 128;
    const int n0   = blockIdx.x * 128;

    // Staging map: f = tid + it*256; row = f & 127 (lane-varying -> conflict-
    // free STS), k4 = (f>>7)*4.
    int srow[4], sk4[4];
    #pragma unroll
    for (int it = 0; it < 4; it++) {
        int f = tid + it * 256;
        srow[it] = f & 127;
        sk4[it]  = (f >> 7) << 2;
    }

    float acc[4][4][4];
    #pragma unroll
    for (int i = 0; i < 4; i++)
        #pragma unroll
        for (int j = 0; j < 4; j++)
            #pragma unroll
            for (int r = 0; r < 4; r++) acc[i][j][r] = 0.f;

    float4 ra[4], rb[4];
    #pragma unroll
    for (int it = 0; it < 4; it++) {
        ra[it] = *(const float4*)&A [(long)(m0 + srow[it]) * K + sk4[it]];
        rb[it] = *(const float4*)&Bw[(long)(n0 + srow[it]) * K + sk4[it]];
    }

    for (int k0 = 0; k0 < K; k0 += 32) {
        // store staged regs -> smem (conflict-free)
        #pragma unroll
        for (int it = 0; it < 4; it++) {
            const int r = srow[it], k4 = sk4[it];
            As[k4+0][r] = f2tf32(ra[it].x); As[k4+1][r] = f2tf32(ra[it].y);
            As[k4+2][r] = f2tf32(ra[it].z); As[k4+3][r] = f2tf32(ra[it].w);
            Bs[k4+0][r] = f2tf32(rb[it].x); Bs[k4+1][r] = f2tf32(rb[it].y);
            Bs[k4+2][r] = f2tf32(rb[it].z); Bs[k4+3][r] = f2tf32(rb[it].w);
        }
        __syncthreads();

        // prefetch next chunk (latency hidden behind the mma loop)
        if (k0 + 32 < K) {
            #pragma unroll
            for (int it = 0; it < 4; it++) {
                ra[it] = *(const float4*)&A [(long)(m0 + srow[it]) * K + k0 + 32 + sk4[it]];
                rb[it] = *(const float4*)&Bw[(long)(n0 + srow[it]) * K + k0 + 32 + sk4[it]];
            }
        }

        #pragma unroll
        for (int kk = 0; kk < 4; kk++) {
            const int kb = kk * 8;
            uint32_t af[4][4], bf[4][2];
            #pragma unroll
            for (int im = 0; im < 4; im++) {
                const int mr = wm * 64 + im * 16 + gid;
                af[im][0] = As[kb + qid    ][mr];
                af[im][1] = As[kb + qid    ][mr + 8];
                af[im][2] = As[kb + qid + 4][mr];
                af[im][3] = As[kb + qid + 4][mr + 8];
            }
            #pragma unroll
            for (int in = 0; in < 4; in++) {
                const int nc = wn * 32 + in * 8 + gid;
                bf[in][0] = Bs[kb + qid    ][nc];
                bf[in][1] = Bs[kb + qid + 4][nc];
            }
            #pragma unroll
            for (int im = 0; im < 4; im++)
                #pragma unroll
                for (int in = 0; in < 4; in++)
                    mma_tf32_16x8x8(acc[im][in], af[im], bf[in]);
        }
        __syncthreads();
    }

    // Epilogue: c0:(gid,2q) c1:(gid,2q+1) c2:(gid+8,2q) c3:(gid+8,2q+1)
    #pragma unroll
    for (int im = 0; im < 4; im++) {
        #pragma unroll
        for (int in = 0; in < 4; in++) {
            const int mbase = m0 + wm * 64 + im * 16 + gid;
            const int nbase = n0 + wn * 32 + in * 8 + qid * 2;
            #pragma unroll
            for (int r = 0; r < 4; r++) {
                const int m = mbase + (r >> 1) * 8;
                const int n = nbase + (r & 1);
                float v = acc[im][in][r] + bias[n];
                if (MODE == 1) {
                    int s = n >> 10;
                    int h = (n >> 6) & 15;
                    int d = n & 63;
                    int b = m >> 11;
                    int t = m & 2047;
                    float* dst = (s == 0) ? g_q : (s == 1 ? g_k : g_v);
                    dst[(((long)(b * H_ + h)) * T_ + t) * D_ + d] = v;
                } else {
                    Cout[(long)m * N + n] = v;
                }
            }
        }
    }
}

// ---------------------------------------------------------------------------
// Windowed causal attention v2.
// Block = 512 threads (16 warps) handles QB2=32 consecutive queries of one
// (b,h): warp w owns queries q0+2w, q0+2w+1. Keys staged in 64-key chunks;
// lane scores keys ks+lane and ks+lane+32 for both queries; online softmax;
// p broadcast through smem; V rows shared across the warp's two queries.
// NOTE: all smem row strides are multiples of 4 floats (16B) — float4
// staging stores require it (stride 66 trapped with misaligned address).
// ---------------------------------------------------------------------------
#define QB2 32
#define CK  64

__global__ __launch_bounds__(512) void attn_win_kernel()
{
    __shared__ float q_s[QB2][64];    // 8 KB
    __shared__ float k_s[CK][68];     // 17.4 KB (pad 68: conflict-free LDS.128)
    __shared__ float v_s[CK][68];     // 17.4 KB (16B-aligned rows)
    __shared__ float p_s[QB2][CK];    // 8 KB

    const int tid  = threadIdx.x;
    const int w    = tid >> 5;
    const int lane = tid & 31;
    const int q0   = blockIdx.x * QB2;
    const int h    = blockIdx.y;
    const int b    = blockIdx.z;

    const long bh   = (long)(b * H_ + h);
    const float* Qp = g_q + bh * T_ * D_;
    const float* Kp = g_k + bh * T_ * D_;
    const float* Vp = g_v + bh * T_ * D_;

    // Load Q tile: 32 x 64 floats = 512 float4, one per thread
    {
        int r  = tid >> 4;
        int c4 = (tid & 15) << 2;
        *(float4*)&q_s[r][c4] = *(const float4*)&Qp[(long)(q0 + r) * D_ + c4];
    }

    const int qa = q0 + 2 * w;
    const int qb = qa + 1;
    int lo_blk = q0 - (WIN_ - 1);
    if (lo_blk < 0) lo_blk = 0;
    lo_blk &= ~(CK - 1);
    const int nchunks = ((q0 + QB2 - 1) - lo_blk) / CK + 1;

    float mA = -1e30f, lA = 0.f, accAx = 0.f, accAy = 0.f;
    float mB = -1e30f, lB = 0.f, accBx = 0.f, accBy = 0.f;

    for (int c = 0; c < nchunks; c++) {
        const int ks = lo_blk + c * CK;
        __syncthreads();
        // Stage K and V chunk: 64 rows x 16 float4 x 2 arrays = 2048 float4
        #pragma unroll
        for (int it = 0; it < 4; it++) {
            int f   = tid + it * 512;
            int idx = f & 1023;
            int r   = idx >> 4;
            int c4  = (idx & 15) << 2;
            int j   = ks + r;
            float4 val = make_float4(0.f, 0.f, 0.f, 0.f);
            if (j < T_) {
                const float* src = (f < 1024) ? Kp : Vp;
                val = *(const float4*)&src[(long)j * D_ + c4];
            }
            if (f < 1024) *(float4*)&k_s[r][c4] = val;
            else          *(float4*)&v_s[r][c4] = val;
        }
        __syncthreads();

        // Skip if chunk entirely outside both queries' windows
        if (ks > qb || ks + CK - 1 < qa - (WIN_ - 1)) continue;

        const int j0 = ks + lane;
        const int j1 = ks + lane + 32;
        const bool vA0 = (j0 <= qa) && (qa - j0 < WIN_);
        const bool vA1 = (j1 <= qa) && (qa - j1 < WIN_);
        const bool vB0 = (j0 <= qb) && (qb - j0 < WIN_);
        const bool vB1 = (j1 <= qb) && (qb - j1 < WIN_);

        float dA0 = 0.f, dA1 = 0.f, dB0 = 0.f, dB1 = 0.f;
        #pragma unroll
        for (int d4 = 0; d4 < 16; d4++) {
            float4 k0v = *(const float4*)&k_s[lane     ][d4 * 4];
            float4 k1v = *(const float4*)&k_s[lane + 32][d4 * 4];
            float4 qAv = *(const float4*)&q_s[2 * w    ][d4 * 4];
            float4 qBv = *(const float4*)&q_s[2 * w + 1][d4 * 4];
            dA0 += qAv.x*k0v.x + qAv.y*k0v.y + qAv.z*k0v.z + qAv.w*k0v.w;
            dA1 += qAv.x*k1v.x + qAv.y*k1v.y + qAv.z*k1v.z + qAv.w*k1v.w;
            dB0 += qBv.x*k0v.x + qBv.y*k0v.y + qBv.z*k0v.z + qBv.w*k0v.w;
            dB1 += qBv.x*k1v.x + qBv.y*k1v.y + qBv.z*k1v.z + qBv.w*k1v.w;
        }
        float sA0 = vA0 ? dA0 * 0.125f : -1e30f;
        float sA1 = vA1 ? dA1 * 0.125f : -1e30f;
        float sB0 = vB0 ? dB0 * 0.125f : -1e30f;
        float sB1 = vB1 ? dB1 * 0.125f : -1e30f;

        float cmA = fmaxf(sA0, sA1), cmB = fmaxf(sB0, sB1);
        #pragma unroll
        for (int off = 16; off > 0; off >>= 1) {
            cmA = fmaxf(cmA, __shfl_xor_sync(0xffffffffu, cmA, off));
            cmB = fmaxf(cmB, __shfl_xor_sync(0xffffffffu, cmB, off));
        }

        const float mAn = fmaxf(mA, cmA), mBn = fmaxf(mB, cmB);
        const float cA  = __expf(mA - mAn), cB = __expf(mB - mBn);
        float pA0 = vA0 ? __expf(sA0 - mAn) : 0.f;
        float pA1 = vA1 ? __expf(sA1 - mAn) : 0.f;
        float pB0 = vB0 ? __expf(sB0 - mBn) : 0.f;
        float pB1 = vB1 ? __expf(sB1 - mBn) : 0.f;

        float psA = pA0 + pA1, psB = pB0 + pB1;
        #pragma unroll
        for (int off = 16; off > 0; off >>= 1) {
            psA += __shfl_xor_sync(0xffffffffu, psA, off);
            psB += __shfl_xor_sync(0xffffffffu, psB, off);
        }

        lA = lA * cA + psA;  mA = mAn;
        lB = lB * cB + psB;  mB = mBn;
        accAx *= cA; accAy *= cA;
        accBx *= cB; accBy *= cB;

        p_s[2*w  ][lane] = pA0;  p_s[2*w  ][lane + 32] = pA1;
        p_s[2*w+1][lane] = pB0;  p_s[2*w+1][lane + 32] = pB1;
        __syncwarp();

        #pragma unroll 4
        for (int jj = 0; jj < CK; jj++) {
            float2 vv = *(const float2*)&v_s[jj][lane * 2];
            float pa = p_s[2*w  ][jj];
            float pb = p_s[2*w+1][jj];
            accAx += pa * vv.x;  accAy += pa * vv.y;
            accBx += pb * vv.x;  accBy += pb * vv.y;
        }
        __syncwarp();
    }

    // out laid out [B,T,H,D] == [B,T,C] for the proj GEMM
    {
        const float invA = 1.f / lA;
        float2 oA; oA.x = accAx * invA; oA.y = accAy * invA;
        *(float2*)&g_att[((long)(b * T_ + qa)) * C_ + h * D_ + lane * 2] = oA;
        const float invB = 1.f / lB;
        float2 oB; oB.x = accBx * invB; oB.y = accBy * invB;
        *(float2*)&g_att[((long)(b * T_ + qb)) * C_ + h * D_ + lane * 2] = oB;
    }
}

// ---------------------------------------------------------------------------
// Launch. Inputs identified by element count (all distinct).
// ---------------------------------------------------------------------------
extern "C" void kernel_launch(void* const* d_in, const int* in_sizes, int n_in,
                              void* d_out, int out_size)
{
    const float* x      = 0;
    const float* qkv_w  = 0;
    const float* qkv_b  = 0;
    const float* proj_w = 0;
    const float* proj_b = 0;

    for (int i = 0; i < n_in; i++) {
        switch (in_sizes[i]) {
            case B_ * T_ * C_:  x      = (const float*)d_in[i]; break; // 8388608
            case T_ * T_:       /* attn_mask — unused */         break; // 4194304
            case 3 * C_ * C_:   qkv_w  = (const float*)d_in[i]; break; // 3145728
            case 3 * C_:        qkv_b  = (const float*)d_in[i]; break; // 3072
            case C_ * C_:       proj_w = (const float*)d_in[i]; break; // 1048576
            case C_:            proj_b = (const float*)d_in[i]; break; // 1024
        }
    }

    float* out = (float*)d_out;

    // QKV: [8192,1024] x [3072,1024]^T -> scatter to g_q/g_k/g_v
    {
        dim3 grid(3 * C_ / 128, (B_ * T_) / 128);
        gemm_tf32<1><<<grid, 256>>>(x, qkv_w, qkv_b, nullptr,
                                    B_ * T_, 3 * C_, C_);
    }
    // Attention
    {
        dim3 grid(T_ / QB2, H_, B_);
        attn_win_kernel<<<grid, 512>>>();
    }
    // Proj: g_att [8192,1024] x [1024,1024]^T -> out
    {
        dim3 grid(C_ / 128, (B_ * T_) / 128);
        gemm_tf32<2><<<grid, 256>>>(nullptr, proj_w, proj_b, out,
                                    B_ * T_, C_, C_);
    }
}

// round 7
// speedup vs baseline: 2.4593x; 1.4682x over previous
#include <cuda_runtime.h>
#include <math.h>
#include <stdint.h>

#define B_    4
#define T_    2048
#define C_    1024
#define H_    16
#define D_    64
#define WIN_  256

// Scratch (device globals; no runtime allocation allowed)
__device__ float g_q[B_*H_*T_*D_];
__device__ float g_k[B_*H_*T_*D_];
__device__ float g_v[B_*H_*T_*D_];
__device__ float g_att[B_*T_*C_];

// ---------------------------------------------------------------------------
// tf32 tensor-core GEMM, NT form: C[m,n] = sum_k A[m,k] * Bw[n,k] + bias[n]
// Block tile 128x128x32, 256 threads (8 warps), warp tile 64x32.
// Smem layout [m][k] with k-stride 36:
//   - LDG: row = f>>3, c4 = (f&7)*4  -> fully coalesced (8 lanes per row)
//   - STS.128 of pre-converted tf32: banks 4*row+c4, conflict-free phases
//   - fragment LDS As2[mr][kb+qid]: banks 4*gid+qid -> 32 distinct, free
// Register prefetch of next k-chunk overlaps LDG with the mma loop.
// MODE 0: plain write. MODE 1: qkv scatter. MODE 2: A = g_att (device-bound).
// ---------------------------------------------------------------------------

__device__ __forceinline__ uint32_t f2tf32(float x) {
    uint32_t r;
    asm("cvt.rna.tf32.f32 %0, %1;" : "=r"(r) : "f"(x));
    return r;
}

__device__ __forceinline__ void mma_tf32_16x8x8(
    float* d, const uint32_t* a, const uint32_t* b)
{
    asm volatile(
        "mma.sync.aligned.m16n8k8.row.col.f32.tf32.tf32.f32 "
        "{%0,%1,%2,%3}, {%4,%5,%6,%7}, {%8,%9}, {%0,%1,%2,%3};"
        : "+f"(d[0]), "+f"(d[1]), "+f"(d[2]), "+f"(d[3])
        : "r"(a[0]), "r"(a[1]), "r"(a[2]), "r"(a[3]),
          "r"(b[0]), "r"(b[1]));
}

#define KPAD 36   // k-stride in words; 144B rows keep 16B alignment

template<int MODE>
__global__ __launch_bounds__(256, 2) void gemm_tf32(
    const float* __restrict__ Aarg,
    const float* __restrict__ Bw,
    const float* __restrict__ bias,
    float* __restrict__ Cout,
    int M, int N, int K)
{
    __shared__ uint32_t As2[128][KPAD];   // [m][k], tf32 bits
    __shared__ uint32_t Bs2[128][KPAD];   // [n][k], tf32 bits

    const float* __restrict__ A = (MODE == 2) ? (const float*)g_att : Aarg;

    const int tid  = threadIdx.x;
    const int w    = tid >> 5;
    const int lane = tid & 31;
    const int gid  = lane >> 2;   // 0..7
    const int qid  = lane & 3;    // 0..3
    const int wm   = w & 1;       // 2 warp-rows of 64
    const int wn   = w >> 1;      // 4 warp-cols of 32
    const int m0   = blockIdx.y * 128;
    const int n0   = blockIdx.x * 128;

    // Staging map (coalesced LDG): f = tid + it*256
    int srow[4], sk4[4];
    #pragma unroll
    for (int it = 0; it < 4; it++) {
        int f = tid + it * 256;
        srow[it] = f >> 3;          // 0..127
        sk4[it]  = (f & 7) << 2;    // 0,4,...,28
    }

    float acc[4][4][4];
    #pragma unroll
    for (int i = 0; i < 4; i++)
        #pragma unroll
        for (int j = 0; j < 4; j++)
            #pragma unroll
            for (int r = 0; r < 4; r++) acc[i][j][r] = 0.f;

    float4 ra[4], rb[4];
    #pragma unroll
    for (int it = 0; it < 4; it++) {
        ra[it] = *(const float4*)&A [(long)(m0 + srow[it]) * K + sk4[it]];
        rb[it] = *(const float4*)&Bw[(long)(n0 + srow[it]) * K + sk4[it]];
    }

    for (int k0 = 0; k0 < K; k0 += 32) {
        // convert in regs, then one STS.128 per float4 (conflict-free)
        #pragma unroll
        for (int it = 0; it < 4; it++) {
            const int r = srow[it], k4 = sk4[it];
            uint4 ua, ub;
            ua.x = f2tf32(ra[it].x); ua.y = f2tf32(ra[it].y);
            ua.z = f2tf32(ra[it].z); ua.w = f2tf32(ra[it].w);
            ub.x = f2tf32(rb[it].x); ub.y = f2tf32(rb[it].y);
            ub.z = f2tf32(rb[it].z); ub.w = f2tf32(rb[it].w);
            *(uint4*)&As2[r][k4] = ua;
            *(uint4*)&Bs2[r][k4] = ub;
        }
        __syncthreads();

        // prefetch next chunk (latency hidden behind the mma loop)
        if (k0 + 32 < K) {
            #pragma unroll
            for (int it = 0; it < 4; it++) {
                ra[it] = *(const float4*)&A [(long)(m0 + srow[it]) * K + k0 + 32 + sk4[it]];
                rb[it] = *(const float4*)&Bw[(long)(n0 + srow[it]) * K + k0 + 32 + sk4[it]];
            }
        }

        #pragma unroll
        for (int kk = 0; kk < 4; kk++) {
            const int kb = kk * 8;
            uint32_t af[4][4], bf[4][2];
            #pragma unroll
            for (int im = 0; im < 4; im++) {
                const int mr = wm * 64 + im * 16 + gid;
                af[im][0] = As2[mr    ][kb + qid];
                af[im][1] = As2[mr + 8][kb + qid];
                af[im][2] = As2[mr    ][kb + qid + 4];
                af[im][3] = As2[mr + 8][kb + qid + 4];
            }
            #pragma unroll
            for (int in = 0; in < 4; in++) {
                const int nc = wn * 32 + in * 8 + gid;
                bf[in][0] = Bs2[nc][kb + qid];
                bf[in][1] = Bs2[nc][kb + qid + 4];
            }
            #pragma unroll
            for (int im = 0; im < 4; im++)
                #pragma unroll
                for (int in = 0; in < 4; in++)
                    mma_tf32_16x8x8(acc[im][in], af[im], bf[in]);
        }
        __syncthreads();
    }

    // Epilogue: c0:(gid,2q) c1:(gid,2q+1) c2:(gid+8,2q) c3:(gid+8,2q+1)
    #pragma unroll
    for (int im = 0; im < 4; im++) {
        #pragma unroll
        for (int in = 0; in < 4; in++) {
            const int mbase = m0 + wm * 64 + im * 16 + gid;
            const int nbase = n0 + wn * 32 + in * 8 + qid * 2;
            #pragma unroll
            for (int r = 0; r < 4; r++) {
                const int m = mbase + (r >> 1) * 8;
                const int n = nbase + (r & 1);
                float v = acc[im][in][r] + bias[n];
                if (MODE == 1) {
                    int s = n >> 10;
                    int h = (n >> 6) & 15;
                    int d = n & 63;
                    int b = m >> 11;
                    int t = m & 2047;
                    float* dst = (s == 0) ? g_q : (s == 1 ? g_k : g_v);
                    dst[(((long)(b * H_ + h)) * T_ + t) * D_ + d] = v;
                } else {
                    Cout[(long)m * N + n] = v;
                }
            }
        }
    }
}

// ---------------------------------------------------------------------------
// Windowed causal attention v2 (unchanged from R6).
// Block = 512 threads (16 warps) handles QB2=32 consecutive queries of one
// (b,h): warp w owns queries q0+2w, q0+2w+1. Keys staged in 64-key chunks;
// online softmax; p broadcast through smem; V rows shared across queries.
// ---------------------------------------------------------------------------
#define QB2 32
#define CK  64

__global__ __launch_bounds__(512) void attn_win_kernel()
{
    __shared__ float q_s[QB2][64];
    __shared__ float k_s[CK][68];
    __shared__ float v_s[CK][68];
    __shared__ float p_s[QB2][CK];

    const int tid  = threadIdx.x;
    const int w    = tid >> 5;
    const int lane = tid & 31;
    const int q0   = blockIdx.x * QB2;
    const int h    = blockIdx.y;
    const int b    = blockIdx.z;

    const long bh   = (long)(b * H_ + h);
    const float* Qp = g_q + bh * T_ * D_;
    const float* Kp = g_k + bh * T_ * D_;
    const float* Vp = g_v + bh * T_ * D_;

    {
        int r  = tid >> 4;
        int c4 = (tid & 15) << 2;
        *(float4*)&q_s[r][c4] = *(const float4*)&Qp[(long)(q0 + r) * D_ + c4];
    }

    const int qa = q0 + 2 * w;
    const int qb = qa + 1;
    int lo_blk = q0 - (WIN_ - 1);
    if (lo_blk < 0) lo_blk = 0;
    lo_blk &= ~(CK - 1);
    const int nchunks = ((q0 + QB2 - 1) - lo_blk) / CK + 1;

    float mA = -1e30f, lA = 0.f, accAx = 0.f, accAy = 0.f;
    float mB = -1e30f, lB = 0.f, accBx = 0.f, accBy = 0.f;

    for (int c = 0; c < nchunks; c++) {
        const int ks = lo_blk + c * CK;
        __syncthreads();
        #pragma unroll
        for (int it = 0; it < 4; it++) {
            int f   = tid + it * 512;
            int idx = f & 1023;
            int r   = idx >> 4;
            int c4  = (idx & 15) << 2;
            int j   = ks + r;
            float4 val = make_float4(0.f, 0.f, 0.f, 0.f);
            if (j < T_) {
                const float* src = (f < 1024) ? Kp : Vp;
                val = *(const float4*)&src[(long)j * D_ + c4];
            }
            if (f < 1024) *(float4*)&k_s[r][c4] = val;
            else          *(float4*)&v_s[r][c4] = val;
        }
        __syncthreads();

        if (ks > qb || ks + CK - 1 < qa - (WIN_ - 1)) continue;

        const int j0 = ks + lane;
        const int j1 = ks + lane + 32;
        const bool vA0 = (j0 <= qa) && (qa - j0 < WIN_);
        const bool vA1 = (j1 <= qa) && (qa - j1 < WIN_);
        const bool vB0 = (j0 <= qb) && (qb - j0 < WIN_);
        const bool vB1 = (j1 <= qb) && (qb - j1 < WIN_);

        float dA0 = 0.f, dA1 = 0.f, dB0 = 0.f, dB1 = 0.f;
        #pragma unroll
        for (int d4 = 0; d4 < 16; d4++) {
            float4 k0v = *(const float4*)&k_s[lane     ][d4 * 4];
            float4 k1v = *(const float4*)&k_s[lane + 32][d4 * 4];
            float4 qAv = *(const float4*)&q_s[2 * w    ][d4 * 4];
            float4 qBv = *(const float4*)&q_s[2 * w + 1][d4 * 4];
            dA0 += qAv.x*k0v.x + qAv.y*k0v.y + qAv.z*k0v.z + qAv.w*k0v.w;
            dA1 += qAv.x*k1v.x + qAv.y*k1v.y + qAv.z*k1v.z + qAv.w*k1v.w;
            dB0 += qBv.x*k0v.x + qBv.y*k0v.y + qBv.z*k0v.z + qBv.w*k0v.w;
            dB1 += qBv.x*k1v.x + qBv.y*k1v.y + qBv.z*k1v.z + qBv.w*k1v.w;
        }
        float sA0 = vA0 ? dA0 * 0.125f : -1e30f;
        float sA1 = vA1 ? dA1 * 0.125f : -1e30f;
        float sB0 = vB0 ? dB0 * 0.125f : -1e30f;
        float sB1 = vB1 ? dB1 * 0.125f : -1e30f;

        float cmA = fmaxf(sA0, sA1), cmB = fmaxf(sB0, sB1);
        #pragma unroll
        for (int off = 16; off > 0; off >>= 1) {
            cmA = fmaxf(cmA, __shfl_xor_sync(0xffffffffu, cmA, off));
            cmB = fmaxf(cmB, __shfl_xor_sync(0xffffffffu, cmB, off));
        }

        const float mAn = fmaxf(mA, cmA), mBn = fmaxf(mB, cmB);
        const float cA  = __expf(mA - mAn), cB = __expf(mB - mBn);
        float pA0 = vA0 ? __expf(sA0 - mAn) : 0.f;
        float pA1 = vA1 ? __expf(sA1 - mAn) : 0.f;
        float pB0 = vB0 ? __expf(sB0 - mBn) : 0.f;
        float pB1 = vB1 ? __expf(sB1 - mBn) : 0.f;

        float psA = pA0 + pA1, psB = pB0 + pB1;
        #pragma unroll
        for (int off = 16; off > 0; off >>= 1) {
            psA += __shfl_xor_sync(0xffffffffu, psA, off);
            psB += __shfl_xor_sync(0xffffffffu, psB, off);
        }

        lA = lA * cA + psA;  mA = mAn;
        lB = lB * cB + psB;  mB = mBn;
        accAx *= cA; accAy *= cA;
        accBx *= cB; accBy *= cB;

        p_s[2*w  ][lane] = pA0;  p_s[2*w  ][lane + 32] = pA1;
        p_s[2*w+1][lane] = pB0;  p_s[2*w+1][lane + 32] = pB1;
        __syncwarp();

        #pragma unroll 4
        for (int jj = 0; jj < CK; jj++) {
            float2 vv = *(const float2*)&v_s[jj][lane * 2];
            float pa = p_s[2*w  ][jj];
            float pb = p_s[2*w+1][jj];
            accAx += pa * vv.x;  accAy += pa * vv.y;
            accBx += pb * vv.x;  accBy += pb * vv.y;
        }
        __syncwarp();
    }

    {
        const float invA = 1.f / lA;
        float2 oA; oA.x = accAx * invA; oA.y = accAy * invA;
        *(float2*)&g_att[((long)(b * T_ + qa)) * C_ + h * D_ + lane * 2] = oA;
        const float invB = 1.f / lB;
        float2 oB; oB.x = accBx * invB; oB.y = accBy * invB;
        *(float2*)&g_att[((long)(b * T_ + qb)) * C_ + h * D_ + lane * 2] = oB;
    }
}

// ---------------------------------------------------------------------------
// Launch. Inputs identified by element count (all distinct).
// ---------------------------------------------------------------------------
extern "C" void kernel_launch(void* const* d_in, const int* in_sizes, int n_in,
                              void* d_out, int out_size)
{
    const float* x      = 0;
    const float* qkv_w  = 0;
    const float* qkv_b  = 0;
    const float* proj_w = 0;
    const float* proj_b = 0;

    for (int i = 0; i < n_in; i++) {
        switch (in_sizes[i]) {
            case B_ * T_ * C_:  x      = (const float*)d_in[i]; break; // 8388608
            case T_ * T_:       /* attn_mask — unused */         break; // 4194304
            case 3 * C_ * C_:   qkv_w  = (const float*)d_in[i]; break; // 3145728
            case 3 * C_:        qkv_b  = (const float*)d_in[i]; break; // 3072
            case C_ * C_:       proj_w = (const float*)d_in[i]; break; // 1048576
            case C_:            proj_b = (const float*)d_in[i]; break; // 1024
        }
    }

    float* out = (float*)d_out;

    // QKV: [8192,1024] x [3072,1024]^T -> scatter to g_q/g_k/g_v
    {
        dim3 grid(3 * C_ / 128, (B_ * T_) / 128);
        gemm_tf32<1><<<grid, 256>>>(x, qkv_w, qkv_b, nullptr,
                                    B_ * T_, 3 * C_, C_);
    }
    // Attention
    {
        dim3 grid(T_ / QB2, H_, B_);
        attn_win_kernel<<<grid, 512>>>();
    }
    // Proj: g_att [8192,1024] x [1024,1024]^T -> out
    {
        dim3 grid(C_ / 128, (B_ * T_) / 128);
        gemm_tf32<2><<<grid, 256>>>(nullptr, proj_w, proj_b, out,
                                    B_ * T_, C_, C_);
    }
}

// round 8
// speedup vs baseline: 3.7567x; 1.5275x over previous
#include <cuda_runtime.h>
#include <math.h>
#include <stdint.h>

#define B_    4
#define T_    2048
#define C_    1024
#define H_    16
#define D_    64
#define WIN_  256

// Scratch (device globals; no runtime allocation allowed)
__device__ float g_q[B_*H_*T_*D_];
__device__ float g_k[B_*H_*T_*D_];
__device__ float g_v[B_*H_*T_*D_];
__device__ float g_att[B_*T_*C_];

__device__ __forceinline__ uint32_t f2tf32(float x) {
    uint32_t r;
    asm("cvt.rna.tf32.f32 %0, %1;" : "=r"(r) : "f"(x));
    return r;
}

__device__ __forceinline__ void mma_tf32_16x8x8(
    float* d, const uint32_t* a, const uint32_t* b)
{
    asm volatile(
        "mma.sync.aligned.m16n8k8.row.col.f32.tf32.tf32.f32 "
        "{%0,%1,%2,%3}, {%4,%5,%6,%7}, {%8,%9}, {%0,%1,%2,%3};"
        : "+f"(d[0]), "+f"(d[1]), "+f"(d[2]), "+f"(d[3])
        : "r"(a[0]), "r"(a[1]), "r"(a[2]), "r"(a[3]),
          "r"(b[0]), "r"(b[1]));
}

// ---------------------------------------------------------------------------
// tf32 tensor-core GEMM (unchanged from R7; 45% tensor pipe).
// ---------------------------------------------------------------------------
#define KPAD 36

template<int MODE>
__global__ __launch_bounds__(256, 2) void gemm_tf32(
    const float* __restrict__ Aarg,
    const float* __restrict__ Bw,
    const float* __restrict__ bias,
    float* __restrict__ Cout,
    int M, int N, int K)
{
    __shared__ uint32_t As2[128][KPAD];
    __shared__ uint32_t Bs2[128][KPAD];

    const float* __restrict__ A = (MODE == 2) ? (const float*)g_att : Aarg;

    const int tid  = threadIdx.x;
    const int w    = tid >> 5;
    const int lane = tid & 31;
    const int gid  = lane >> 2;
    const int qid  = lane & 3;
    const int wm   = w & 1;
    const int wn   = w >> 1;
    const int m0   = blockIdx.y * 128;
    const int n0   = blockIdx.x * 128;

    int srow[4], sk4[4];
    #pragma unroll
    for (int it = 0; it < 4; it++) {
        int f = tid + it * 256;
        srow[it] = f >> 3;
        sk4[it]  = (f & 7) << 2;
    }

    float acc[4][4][4];
    #pragma unroll
    for (int i = 0; i < 4; i++)
        #pragma unroll
        for (int j = 0; j < 4; j++)
            #pragma unroll
            for (int r = 0; r < 4; r++) acc[i][j][r] = 0.f;

    float4 ra[4], rb[4];
    #pragma unroll
    for (int it = 0; it < 4; it++) {
        ra[it] = *(const float4*)&A [(long)(m0 + srow[it]) * K + sk4[it]];
        rb[it] = *(const float4*)&Bw[(long)(n0 + srow[it]) * K + sk4[it]];
    }

    for (int k0 = 0; k0 < K; k0 += 32) {
        #pragma unroll
        for (int it = 0; it < 4; it++) {
            const int r = srow[it], k4 = sk4[it];
            uint4 ua, ub;
            ua.x = f2tf32(ra[it].x); ua.y = f2tf32(ra[it].y);
            ua.z = f2tf32(ra[it].z); ua.w = f2tf32(ra[it].w);
            ub.x = f2tf32(rb[it].x); ub.y = f2tf32(rb[it].y);
            ub.z = f2tf32(rb[it].z); ub.w = f2tf32(rb[it].w);
            *(uint4*)&As2[r][k4] = ua;
            *(uint4*)&Bs2[r][k4] = ub;
        }
        __syncthreads();

        if (k0 + 32 < K) {
            #pragma unroll
            for (int it = 0; it < 4; it++) {
                ra[it] = *(const float4*)&A [(long)(m0 + srow[it]) * K + k0 + 32 + sk4[it]];
                rb[it] = *(const float4*)&Bw[(long)(n0 + srow[it]) * K + k0 + 32 + sk4[it]];
            }
        }

        #pragma unroll
        for (int kk = 0; kk < 4; kk++) {
            const int kb = kk * 8;
            uint32_t af[4][4], bf[4][2];
            #pragma unroll
            for (int im = 0; im < 4; im++) {
                const int mr = wm * 64 + im * 16 + gid;
                af[im][0] = As2[mr    ][kb + qid];
                af[im][1] = As2[mr + 8][kb + qid];
                af[im][2] = As2[mr    ][kb + qid + 4];
                af[im][3] = As2[mr + 8][kb + qid + 4];
            }
            #pragma unroll
            for (int in = 0; in < 4; in++) {
                const int nc = wn * 32 + in * 8 + gid;
                bf[in][0] = Bs2[nc][kb + qid];
                bf[in][1] = Bs2[nc][kb + qid + 4];
            }
            #pragma unroll
            for (int im = 0; im < 4; im++)
                #pragma unroll
                for (int in = 0; in < 4; in++)
                    mma_tf32_16x8x8(acc[im][in], af[im], bf[in]);
        }
        __syncthreads();
    }

    #pragma unroll
    for (int im = 0; im < 4; im++) {
        #pragma unroll
        for (int in = 0; in < 4; in++) {
            const int mbase = m0 + wm * 64 + im * 16 + gid;
            const int nbase = n0 + wn * 32 + in * 8 + qid * 2;
            #pragma unroll
            for (int r = 0; r < 4; r++) {
                const int m = mbase + (r >> 1) * 8;
                const int n = nbase + (r & 1);
                float v = acc[im][in][r] + bias[n];
                if (MODE == 1) {
                    int s = n >> 10;
                    int h = (n >> 6) & 15;
                    int d = n & 63;
                    int b = m >> 11;
                    int t = m & 2047;
                    float* dst = (s == 0) ? g_q : (s == 1 ? g_k : g_v);
                    dst[(((long)(b * H_ + h)) * T_ + t) * D_ + d] = v;
                } else {
                    Cout[(long)m * N + n] = v;
                }
            }
        }
    }
}

// ---------------------------------------------------------------------------
// Tensor-core windowed attention.
// Block = 256 threads (8 warps) handles QT=128 queries of one (b,h); warp w
// owns 16 queries [qw, qw+15] with Q in registers as tf32 fragments.
// Keys in CK2=32 chunks, staged pre-converted to tf32:
//   k_s[key][dim]  stride 68 -> QK b-frag LDS banks 4g+q (conflict-free)
//   v_s[dim][key]  stride 40 -> PV b-frag banks 8g+q (2-way), STS conflict-free
// S fragments masked via (unsigned)(q-j)<WIN, online softmax on fragments,
// P routed through per-warp smem (tf32 C-layout != A-layout), then PV mma.
// Masked-row garbage self-corrects: first real key gives corr=exp(-1e30-m)=0.
// ---------------------------------------------------------------------------
#define QT  128
#define CK2 32

__global__ __launch_bounds__(256, 2) void attn_mma_kernel()
{
    __shared__ uint32_t k_s[CK2][68];       // [key][dim] tf32   8.7 KB
    __shared__ uint32_t v_s[64][40];        // [dim][key] tf32  10.2 KB
    __shared__ uint32_t p_s[8][16][40];     // per-warp P tf32  20.5 KB

    const int tid  = threadIdx.x;
    const int w    = tid >> 5;
    const int lane = tid & 31;
    const int g    = lane >> 2;   // 0..7
    const int q    = lane & 3;    // 0..3
    const int q0   = blockIdx.x * QT;
    const int h    = blockIdx.y;
    const int b    = blockIdx.z;

    const long bh   = (long)(b * H_ + h);
    const float* Qp = g_q + bh * T_ * D_;
    const float* Kp = g_k + bh * T_ * D_;
    const float* Vp = g_v + bh * T_ * D_;

    const int qw  = q0 + w * 16;     // warp's first query
    const int qg0 = qw + g;
    const int qg1 = qw + g + 8;

    // Q fragments (scale 1/8 folded), resident whole kernel: 32 regs
    uint32_t aq[8][4];
    #pragma unroll
    for (int kk = 0; kk < 8; kk++) {
        aq[kk][0] = f2tf32(Qp[(long)qg0 * D_ + kk * 8 + q    ] * 0.125f);
        aq[kk][1] = f2tf32(Qp[(long)qg1 * D_ + kk * 8 + q    ] * 0.125f);
        aq[kk][2] = f2tf32(Qp[(long)qg0 * D_ + kk * 8 + q + 4] * 0.125f);
        aq[kk][3] = f2tf32(Qp[(long)qg1 * D_ + kk * 8 + q + 4] * 0.125f);
    }

    int lo_blk = q0 - (WIN_ - 1);
    if (lo_blk < 0) lo_blk = 0;
    lo_blk &= ~(CK2 - 1);
    const int nchunks = ((q0 + QT - 1) - lo_blk) / CK2 + 1;

    float o[8][4];
    #pragma unroll
    for (int dt = 0; dt < 8; dt++)
        #pragma unroll
        for (int r = 0; r < 4; r++) o[dt][r] = 0.f;
    float m0r = -1e30f, m1r = -1e30f, l0 = 0.f, l1 = 0.f;

    for (int c = 0; c < nchunks; c++) {
        const int ks = lo_blk + c * CK2;
        __syncthreads();
        // Stage K: 32 keys x 64 dims = 512 float4; j = f>>4, quad = f&15
        #pragma unroll
        for (int it = 0; it < 2; it++) {
            int f    = tid + it * 256;
            int j    = f >> 4;
            int qd   = (f & 15) << 2;
            float4 kv = *(const float4*)&Kp[(long)(ks + j) * D_ + qd];
            uint4 uk;
            uk.x = f2tf32(kv.x); uk.y = f2tf32(kv.y);
            uk.z = f2tf32(kv.z); uk.w = f2tf32(kv.w);
            *(uint4*)&k_s[j][qd] = uk;
        }
        // Stage V transposed: j = f&31 (lane-varying -> STS conflict-free)
        #pragma unroll
        for (int it = 0; it < 2; it++) {
            int f   = tid + it * 256;
            int j   = f & 31;
            int dq  = (f >> 5) << 2;
            float4 vv = *(const float4*)&Vp[(long)(ks + j) * D_ + dq];
            v_s[dq + 0][j] = f2tf32(vv.x);
            v_s[dq + 1][j] = f2tf32(vv.y);
            v_s[dq + 2][j] = f2tf32(vv.z);
            v_s[dq + 3][j] = f2tf32(vv.w);
        }
        __syncthreads();

        // Skip chunks outside this warp's 16-query window span
        if (ks > qw + 15 || ks + CK2 - 1 < qw - (WIN_ - 1)) continue;

        // S = Q*K^T : 4 n-tiles x 8 k-steps
        float s[4][4];
        #pragma unroll
        for (int nt = 0; nt < 4; nt++)
            #pragma unroll
            for (int r = 0; r < 4; r++) s[nt][r] = 0.f;
        #pragma unroll
        for (int kk = 0; kk < 8; kk++) {
            uint32_t bf[4][2];
            #pragma unroll
            for (int nt = 0; nt < 4; nt++) {
                bf[nt][0] = k_s[nt * 8 + g][kk * 8 + q];
                bf[nt][1] = k_s[nt * 8 + g][kk * 8 + q + 4];
            }
            #pragma unroll
            for (int nt = 0; nt < 4; nt++)
                mma_tf32_16x8x8(s[nt], aq[kk], bf[nt]);
        }

        // Mask: valid iff 0 <= q - j < WIN  (single unsigned compare)
        #pragma unroll
        for (int nt = 0; nt < 4; nt++) {
            const int j0 = ks + nt * 8 + 2 * q;
            const int j1 = j0 + 1;
            s[nt][0] = ((unsigned)(qg0 - j0) < WIN_) ? s[nt][0] : -1e30f;
            s[nt][1] = ((unsigned)(qg0 - j1) < WIN_) ? s[nt][1] : -1e30f;
            s[nt][2] = ((unsigned)(qg1 - j0) < WIN_) ? s[nt][2] : -1e30f;
            s[nt][3] = ((unsigned)(qg1 - j1) < WIN_) ? s[nt][3] : -1e30f;
        }

        // Row maxes over the chunk (thread-local then quad shfl)
        float cm0 = -1e30f, cm1 = -1e30f;
        #pragma unroll
        for (int nt = 0; nt < 4; nt++) {
            cm0 = fmaxf(cm0, fmaxf(s[nt][0], s[nt][1]));
            cm1 = fmaxf(cm1, fmaxf(s[nt][2], s[nt][3]));
        }
        cm0 = fmaxf(cm0, __shfl_xor_sync(0xffffffffu, cm0, 1));
        cm0 = fmaxf(cm0, __shfl_xor_sync(0xffffffffu, cm0, 2));
        cm1 = fmaxf(cm1, __shfl_xor_sync(0xffffffffu, cm1, 1));
        cm1 = fmaxf(cm1, __shfl_xor_sync(0xffffffffu, cm1, 2));

        const float m0n = fmaxf(m0r, cm0), m1n = fmaxf(m1r, cm1);
        const float c0  = __expf(m0r - m0n), c1 = __expf(m1r - m1n);

        float p[4][4];
        float ps0 = 0.f, ps1 = 0.f;
        #pragma unroll
        for (int nt = 0; nt < 4; nt++) {
            p[nt][0] = __expf(s[nt][0] - m0n);
            p[nt][1] = __expf(s[nt][1] - m0n);
            p[nt][2] = __expf(s[nt][2] - m1n);
            p[nt][3] = __expf(s[nt][3] - m1n);
            ps0 += p[nt][0] + p[nt][1];
            ps1 += p[nt][2] + p[nt][3];
        }
        ps0 += __shfl_xor_sync(0xffffffffu, ps0, 1);
        ps0 += __shfl_xor_sync(0xffffffffu, ps0, 2);
        ps1 += __shfl_xor_sync(0xffffffffu, ps1, 1);
        ps1 += __shfl_xor_sync(0xffffffffu, ps1, 2);

        l0 = l0 * c0 + ps0;  m0r = m0n;
        l1 = l1 * c1 + ps1;  m1r = m1n;
        #pragma unroll
        for (int dt = 0; dt < 8; dt++) {
            o[dt][0] *= c0;  o[dt][1] *= c0;
            o[dt][2] *= c1;  o[dt][3] *= c1;
        }

        // P -> per-warp smem (tf32 bits), C-layout (cols 2q,2q+1)
        #pragma unroll
        for (int nt = 0; nt < 4; nt++) {
            uint2 u0, u1;
            u0.x = f2tf32(p[nt][0]); u0.y = f2tf32(p[nt][1]);
            u1.x = f2tf32(p[nt][2]); u1.y = f2tf32(p[nt][3]);
            *(uint2*)&p_s[w][g    ][nt * 8 + 2 * q] = u0;
            *(uint2*)&p_s[w][g + 8][nt * 8 + 2 * q] = u1;
        }
        __syncwarp();

        // O += P * V : 4 k-steps (keys) x 8 dim-tiles
        #pragma unroll
        for (int kk = 0; kk < 4; kk++) {
            uint32_t ap[4];
            ap[0] = p_s[w][g    ][kk * 8 + q];
            ap[1] = p_s[w][g + 8][kk * 8 + q];
            ap[2] = p_s[w][g    ][kk * 8 + q + 4];
            ap[3] = p_s[w][g + 8][kk * 8 + q + 4];
            #pragma unroll
            for (int dt = 0; dt < 8; dt++) {
                uint32_t bv[2];
                bv[0] = v_s[dt * 8 + g][kk * 8 + q];
                bv[1] = v_s[dt * 8 + g][kk * 8 + q + 4];
                mma_tf32_16x8x8(o[dt], ap, bv);
            }
        }
    }

    // Epilogue: out [B,T,H,D] == [B,T,C]
    const float i0 = 1.f / l0, i1 = 1.f / l1;
    #pragma unroll
    for (int dt = 0; dt < 8; dt++) {
        const int d = dt * 8 + 2 * q;
        float2 o0; o0.x = o[dt][0] * i0; o0.y = o[dt][1] * i0;
        float2 o1; o1.x = o[dt][2] * i1; o1.y = o[dt][3] * i1;
        *(float2*)&g_att[((long)(b * T_ + qg0)) * C_ + h * D_ + d] = o0;
        *(float2*)&g_att[((long)(b * T_ + qg1)) * C_ + h * D_ + d] = o1;
    }
}

// ---------------------------------------------------------------------------
// Launch. Inputs identified by element count (all distinct).
// ---------------------------------------------------------------------------
extern "C" void kernel_launch(void* const* d_in, const int* in_sizes, int n_in,
                              void* d_out, int out_size)
{
    const float* x      = 0;
    const float* qkv_w  = 0;
    const float* qkv_b  = 0;
    const float* proj_w = 0;
    const float* proj_b = 0;

    for (int i = 0; i < n_in; i++) {
        switch (in_sizes[i]) {
            case B_ * T_ * C_:  x      = (const float*)d_in[i]; break; // 8388608
            case T_ * T_:       /* attn_mask — unused */         break; // 4194304
            case 3 * C_ * C_:   qkv_w  = (const float*)d_in[i]; break; // 3145728
            case 3 * C_:        qkv_b  = (const float*)d_in[i]; break; // 3072
            case C_ * C_:       proj_w = (const float*)d_in[i]; break; // 1048576
            case C_:            proj_b = (const float*)d_in[i]; break; // 1024
        }
    }

    float* out = (float*)d_out;

    // QKV: [8192,1024] x [3072,1024]^T -> scatter to g_q/g_k/g_v
    {
        dim3 grid(3 * C_ / 128, (B_ * T_) / 128);
        gemm_tf32<1><<<grid, 256>>>(x, qkv_w, qkv_b, nullptr,
                                    B_ * T_, 3 * C_, C_);
    }
    // Attention (tensor-core)
    {
        dim3 grid(T_ / QT, H_, B_);
        attn_mma_kernel<<<grid, 256>>>();
    }
    // Proj: g_att [8192,1024] x [1024,1024]^T -> out
    {
        dim3 grid(C_ / 128, (B_ * T_) / 128);
        gemm_tf32<2><<<grid, 256>>>(nullptr, proj_w, proj_b, out,
                                    B_ * T_, C_, C_);
    }
}